// round 13
// baseline (speedup 1.0000x reference)
#include <cuda_runtime.h>
#include <cuda_bf16.h>
#include <math.h>

typedef unsigned long long ull;
typedef unsigned u32;

#define NCTA 128
#define TPB 512
#define WSROW 1032                      // bf16 per weight row (pad -> conflict-free)
#define WS_BYTES (2 * 24 * WSROW * 2)   // 99072
#define ASROWB 272                      // bytes per A row (136 bf16, pad)
#define AS_PLANEB (64 * ASROWB)         // 17408
#define AS_BUFB (2 * AS_PLANEB)         // 34816
#define SMEMSZ (WS_BYTES + 3 * AS_BUFB) // 203520

__device__ float g_EW[128 * 3 * 1024];
__device__ float g_Wc[1024 * 128];
__device__ float g_bc[128];
__device__ float g_y[64u * 512u * 1024u];
__device__ __align__(16) __nv_bfloat16 g_hG[2 * 2 * 64 * 1024]; // [parity][plane][b][k]
__device__ u32 g_cnt;
__device__ u32 g_gen;

__device__ __forceinline__ u32 su32(const void* p) {
    u32 a;
    asm("{ .reg .u64 t; cvta.to.shared.u64 t, %1; cvt.u32.u64 %0, t; }" : "=r"(a) : "l"(p));
    return a;
}
__device__ __forceinline__ void cpa16(u32 d, const void* s) {
    asm volatile("cp.async.cg.shared.global [%0], [%1], 16;" :: "r"(d), "l"(s));
}
__device__ __forceinline__ void ldsm4(u32 a, u32& r0, u32& r1, u32& r2, u32& r3) {
    asm volatile("ldmatrix.sync.aligned.m8n8.x4.shared.b16 {%0,%1,%2,%3}, [%4];"
                 : "=r"(r0), "=r"(r1), "=r"(r2), "=r"(r3) : "r"(a));
}
__device__ __forceinline__ void ldsm2(u32 a, u32& r0, u32& r1) {
    asm volatile("ldmatrix.sync.aligned.m8n8.x2.shared.b16 {%0,%1}, [%2];"
                 : "=r"(r0), "=r"(r1) : "r"(a));
}
__device__ __forceinline__ void mma16816(float* d, const u32* a, const u32* b) {
    asm volatile("mma.sync.aligned.m16n8k16.row.col.f32.bf16.bf16.f32 "
        "{%0,%1,%2,%3},{%4,%5,%6,%7},{%8,%9},{%0,%1,%2,%3};"
        : "+f"(d[0]), "+f"(d[1]), "+f"(d[2]), "+f"(d[3])
        : "r"(a[0]), "r"(a[1]), "r"(a[2]), "r"(a[3]), "r"(b[0]), "r"(b[1]));
}
__device__ __forceinline__ float fsig(float x) {
    return __fdividef(1.0f, 1.0f + __expf(-x));
}
__device__ __forceinline__ float ftanh(float x) {
    float e = __expf(-2.0f * fabsf(x));
    float t = __fdividef(1.0f - e, 1.0f + e);
    return copysignf(t, x);
}

// ---------------- prep: EW table -------------------------------------------
__global__ __launch_bounds__(256) void prep_ew(
    const float* __restrict__ emb,
    const float* __restrict__ Wir, const float* __restrict__ bir,
    const float* __restrict__ Wiz, const float* __restrict__ biz,
    const float* __restrict__ Win, const float* __restrict__ bin_)
{
    __shared__ float se[128];
    int v = blockIdx.x, tid = threadIdx.x;
    if (tid < 128) se[tid] = emb[v * 128 + tid];
    __syncthreads();
    for (int i = tid; i < 3072; i += 256) {
        int g = i >> 10, j = i & 1023;
        const float* W  = (g == 0) ? Wir : (g == 1) ? Wiz : Win;
        const float* bb = (g == 0) ? bir : (g == 1) ? biz : bin_;
        float acc = bb[j];
        #pragma unroll 8
        for (int e = 0; e < 128; ++e) acc += se[e] * W[e * 1024 + j];
        g_EW[v * 3072 + i] = acc;
    }
}

// ---------------- prep: carry -> hG parity0, bc, counters -------------------
__global__ __launch_bounds__(256) void prep_misc(
    const float* __restrict__ carry, const float* __restrict__ bh,
    const float* __restrict__ Wo,    const float* __restrict__ bo)
{
    int bx = blockIdx.x, tid = threadIdx.x;
    if (bx < 64) {
        int b = bx;
        for (int i = 0; i < 4; ++i) {
            int k = tid + i * 256;
            float f = carry[b * 1024 + k];
            __nv_bfloat16 hi = __float2bfloat16(f);
            __nv_bfloat16 lo = __float2bfloat16(f - __bfloat162float(hi));
            g_hG[b * 1024 + k]         = hi;
            g_hG[65536 + b * 1024 + k] = lo;
        }
    } else {
        if (tid < 128) {
            float acc = bo[tid];
            for (int m = 0; m < 1024; ++m) acc += bh[m] * Wo[m * 128 + tid];
            g_bc[tid] = acc;
        }
        if (tid == 0) { g_cnt = 0u; g_gen = 0u; }
    }
}

// ---------------- tiled fp32 GEMM (Wc precompute + final logits) ------------
__global__ __launch_bounds__(256) void gemm128(
    const float* __restrict__ A, const float* __restrict__ Bm,
    const float* __restrict__ bias, float* __restrict__ C)
{
    __shared__ float As[32][132];
    __shared__ float Bs[32][128];
    int tid = threadIdx.x, tx = tid & 15, ty = tid >> 4, m0 = blockIdx.x * 128;
    float acc[8][8];
    #pragma unroll
    for (int i = 0; i < 8; ++i)
        #pragma unroll
        for (int j = 0; j < 8; ++j) acc[i][j] = bias ? bias[tx * 8 + j] : 0.0f;
    for (int k0 = 0; k0 < 1024; k0 += 32) {
        __syncthreads();
        #pragma unroll
        for (int i = 0; i < 4; ++i) {
            int idx = tid + i * 256, m = idx >> 3, q = idx & 7;
            float4 v = *(const float4*)(A + (size_t)(m0 + m) * 1024 + k0 + q * 4);
            As[q * 4 + 0][m] = v.x; As[q * 4 + 1][m] = v.y;
            As[q * 4 + 2][m] = v.z; As[q * 4 + 3][m] = v.w;
        }
        #pragma unroll
        for (int i = 0; i < 4; ++i) {
            int idx = tid + i * 256, r = idx >> 5, q = idx & 31;
            *(float4*)(&Bs[r][q * 4]) = *(const float4*)(Bm + (size_t)(k0 + r) * 128 + q * 4);
        }
        __syncthreads();
        #pragma unroll 4
        for (int kk = 0; kk < 32; ++kk) {
            float4 a0 = *(const float4*)(&As[kk][ty * 8]);
            float4 a1 = *(const float4*)(&As[kk][ty * 8 + 4]);
            float4 b0 = *(const float4*)(&Bs[kk][tx * 8]);
            float4 b1 = *(const float4*)(&Bs[kk][tx * 8 + 4]);
            float av[8] = {a0.x, a0.y, a0.z, a0.w, a1.x, a1.y, a1.z, a1.w};
            float bv[8] = {b0.x, b0.y, b0.z, b0.w, b1.x, b1.y, b1.z, b1.w};
            #pragma unroll
            for (int i = 0; i < 8; ++i)
                #pragma unroll
                for (int j = 0; j < 8; ++j) acc[i][j] = fmaf(av[i], bv[j], acc[i][j]);
        }
    }
    #pragma unroll
    for (int i = 0; i < 8; ++i) {
        float* cp = C + (size_t)(m0 + ty * 8 + i) * 128 + tx * 8;
        *(float4*)cp       = make_float4(acc[i][0], acc[i][1], acc[i][2], acc[i][3]);
        *(float4*)(cp + 4) = make_float4(acc[i][4], acc[i][5], acc[i][6], acc[i][7]);
    }
}

// ---------------- staging: h chunk (k128) into As buf 0..2 ------------------
__device__ __forceinline__ void stageA(u32 as_base, int buf, int chunk, int p, int tid)
{
    const __nv_bfloat16* src0 = g_hG + (size_t)p * 131072;
    #pragma unroll
    for (int i2 = 0; i2 < 4; ++i2) {
        int u = tid + i2 * TPB;                    // 0..2047
        int plane = u >> 10, rem = u & 1023, b = rem >> 4, kc = rem & 15;
        const __nv_bfloat16* src = src0 + plane * 65536 + b * 1024 + chunk * 128 + kc * 8;
        u32 dst = as_base + buf * AS_BUFB + plane * AS_PLANEB + b * ASROWB + kc * 16;
        cpa16(dst, src);
    }
    asm volatile("cp.async.commit_group;" ::: "memory");
}

// ---------------- persistent mma.sync GRU scan (512 thr, 8-way k-split) -----
__global__ void __launch_bounds__(TPB, 1) scan_kernel(
    const int* __restrict__ toks,
    const float* __restrict__ Whr, const float* __restrict__ Whz,
    const float* __restrict__ Whn, const float* __restrict__ bhn,
    const float* __restrict__ carry, float* __restrict__ outc)
{
    extern __shared__ char sm[];
    __nv_bfloat16* Ws = (__nv_bfloat16*)sm;
    const u32 smb = su32(sm);
    const u32 as_base = smb + WS_BYTES;
    float* redA = (float*)(sm + WS_BYTES);                 // buf0 region (kq 0..3)
    float* redB = (float*)(sm + WS_BYTES + 2 * AS_BUFB);   // buf2 region (kq 4..7)

    const int tid = threadIdx.x, bx = blockIdx.x;
    const int lane = tid & 31, w = tid >> 5;
    const int kq = w >> 1, mpair = w & 1;    // kq 0..7, one k16-segment each
    const int j0 = bx * 8;
    const int c0 = (lane & 3) * 2;

    // ---- weights -> smem bf16 hi/lo, once ----
    for (int idx = tid; idx < 24 * 1024; idx += TPB) {
        int c = idx >> 10, k = idx & 1023;
        int g = c >> 3, jl = c & 7;
        const float* Wg = (g == 0) ? Whr : (g == 1) ? Whz : Whn;
        float wv = Wg[(size_t)k * 1024 + j0 + jl];
        __nv_bfloat16 hi = __float2bfloat16(wv);
        Ws[c * WSROW + k] = hi;
        Ws[24 * WSROW + c * WSROW + k] = __float2bfloat16(wv - __bfloat162float(hi));
    }

    // ---- update owners: warps kq<4, combo (mt,h2)=(kq&1, kq>>1) ----
    const bool owner = (kq < 4);
    const int mt_o = kq & 1, h2_o = (kq >> 1) & 1;
    const int b_o = 32 * mpair + 16 * mt_o + (lane >> 2) + 8 * h2_o;
    float hreg[2], bhn2[2];
    if (owner) {
        bhn2[0] = bhn[j0 + c0]; bhn2[1] = bhn[j0 + c0 + 1];
        hreg[0] = carry[b_o * 1024 + j0 + c0];
        hreg[1] = carry[b_o * 1024 + j0 + c0 + 1];
    }
    __syncthreads();

    const u32 aAddr0 = as_base + (32 * mpair + (lane & 15)) * ASROWB + (lane >> 4) * 16;
    const u32 bAddr0 = smb + ((lane & 7) * WSROW) * 2 + ((lane >> 3) & 1) * 16;

    for (int t = 0; t < 512; ++t) {
        const int p = t & 1;
        stageA(as_base, 0, 0, p, tid);
        stageA(as_base, 1, 1, p, tid);

        // prefetch token + EW rows (L2-resident) for the tail
        float2 er, ez, en;
        if (owner) {
            int tok = toks[b_o * 512 + t];
            const float* ewp = g_EW + (size_t)tok * 3072 + j0 + c0;
            er = *(const float2*)ewp;
            ez = *(const float2*)(ewp + 1024);
            en = *(const float2*)(ewp + 2048);
        }

        float acc[2][3][4];
        float* accf = &acc[0][0][0];
        #pragma unroll
        for (int i = 0; i < 24; ++i) accf[i] = 0.0f;

        #pragma unroll 1
        for (int c = 0; c < 8; ++c) {
            if (c < 7) asm volatile("cp.async.wait_group 1;" ::: "memory");
            else       asm volatile("cp.async.wait_group 0;" ::: "memory");
            __syncthreads();
            if (c < 6) stageA(as_base, (c + 2) % 3, c + 2, p, tid);
            const u32 abuf = aAddr0 + (u32)((c % 3) * AS_BUFB);
            const u32 bk = (u32)(c * 256);
            {
                const int ks = kq;               // this warp's k16-segment
                u32 aH[2][4], aL[2][4], bH[3][2], bL[3][2];
                #pragma unroll
                for (int mt = 0; mt < 2; ++mt) {
                    u32 a = abuf + mt * (16 * ASROWB) + ks * 32;
                    ldsm4(a, aH[mt][0], aH[mt][1], aH[mt][2], aH[mt][3]);
                    ldsm4(a + AS_PLANEB, aL[mt][0], aL[mt][1], aL[mt][2], aL[mt][3]);
                }
                #pragma unroll
                for (int nt = 0; nt < 3; ++nt) {
                    u32 b = bAddr0 + nt * (8 * WSROW * 2) + bk + ks * 32;
                    ldsm2(b, bH[nt][0], bH[nt][1]);
                    ldsm2(b + 24 * WSROW * 2, bL[nt][0], bL[nt][1]);
                }
                #pragma unroll
                for (int mt = 0; mt < 2; ++mt)
                    #pragma unroll
                    for (int nt = 0; nt < 3; ++nt) {
                        mma16816(acc[mt][nt], aH[mt], bH[nt]);
                        mma16816(acc[mt][nt], aH[mt], bL[nt]);
                        mma16816(acc[mt][nt], aL[mt], bH[nt]);
                    }
            }
        }

        // ---- publish partials (rows padded to 25; split across buf0/buf2) --
        {
            float* rp = owner ? (redA + tid * 25) : (redB + (tid - 256) * 25);
            #pragma unroll
            for (int i = 0; i < 24; ++i) rp[i] = accf[i];
        }
        __syncthreads();

        // ---- owners: gather 8 partials, GRU update ----
        if (owner) {
            float s6[6];
            #pragma unroll
            for (int nt = 0; nt < 3; ++nt)
                #pragma unroll
                for (int i = 0; i < 2; ++i) {
                    int idx = mt_o * 12 + nt * 4 + 2 * h2_o + i;
                    float v = 0.0f;
                    #pragma unroll
                    for (int q2 = 0; q2 < 4; ++q2)
                        v += redA[(q2 * 64 + mpair * 32 + lane) * 25 + idx];
                    #pragma unroll
                    for (int q2 = 0; q2 < 4; ++q2)
                        v += redB[(q2 * 64 + mpair * 32 + lane) * 25 + idx];
                    s6[nt * 2 + i] = v;
                }
            float hn[2];
            #pragma unroll
            for (int i = 0; i < 2; ++i) {
                float rr = fsig((i ? er.y : er.x) + s6[0 + i]);
                float zz = fsig((i ? ez.y : ez.x) + s6[2 + i]);
                float nn = ftanh((i ? en.y : en.x) + rr * (s6[4 + i] + bhn2[i]));
                hn[i] = (1.0f - zz) * nn + zz * hreg[i];
                hreg[i] = hn[i];
            }
            *(float2*)(g_y + (size_t)(b_o * 512 + t) * 1024 + j0 + c0) =
                make_float2(hn[0], hn[1]);
            __nv_bfloat16 h0 = __float2bfloat16(hn[0]);
            __nv_bfloat16 h1 = __float2bfloat16(hn[1]);
            __nv_bfloat16 l0 = __float2bfloat16(hn[0] - __bfloat162float(h0));
            __nv_bfloat16 l1 = __float2bfloat16(hn[1] - __bfloat162float(h1));
            int pd = (p ^ 1) * 131072 + b_o * 1024 + j0 + c0;
            *(u32*)(g_hG + pd) =
                (u32)__bfloat16_as_ushort(h0) | ((u32)__bfloat16_as_ushort(h1) << 16);
            *(u32*)(g_hG + pd + 65536) =
                (u32)__bfloat16_as_ushort(l0) | ((u32)__bfloat16_as_ushort(l1) << 16);
            if (t == 511)
                *(float2*)(outc + b_o * 1024 + j0 + c0) = make_float2(hn[0], hn[1]);
            __threadfence();
        }

        // ---- grid barrier (fence-light, monotonic) ----
        __syncthreads();
        if (tid == 0) {
            u32 target = (u32)(t + 1) * (u32)NCTA, old;
            asm volatile("atom.acq_rel.gpu.add.u32 %0, [%1], 1;"
                         : "=r"(old) : "l"(&g_cnt) : "memory");
            if (old == target - 1u) {
                asm volatile("st.release.gpu.u32 [%0], %1;"
                             :: "l"(&g_gen), "r"((u32)(t + 1)) : "memory");
            } else {
                u32 v;
                do {
                    asm volatile("ld.acquire.gpu.u32 %0, [%1];" : "=r"(v) : "l"(&g_gen) : "memory");
                } while (v < (u32)(t + 1));
            }
        }
        __syncthreads();
    }
}

// ---------------- launch ----------------------------------------------------
extern "C" void kernel_launch(void* const* d_in, const int* in_sizes, int n_in,
                              void* d_out, int out_size)
{
    const int*   toks  = (const int*)  d_in[0];
    const float* carry = (const float*)d_in[1];
    const float* emb   = (const float*)d_in[2];
    const float* Wir   = (const float*)d_in[3];
    const float* bir   = (const float*)d_in[4];
    const float* Whr   = (const float*)d_in[5];
    const float* Wiz   = (const float*)d_in[6];
    const float* biz   = (const float*)d_in[7];
    const float* Whz   = (const float*)d_in[8];
    const float* Win   = (const float*)d_in[9];
    const float* bin_  = (const float*)d_in[10];
    const float* Whn   = (const float*)d_in[11];
    const float* bhn   = (const float*)d_in[12];
    const float* Wh    = (const float*)d_in[13];
    const float* bh    = (const float*)d_in[14];
    const float* Wo    = (const float*)d_in[15];
    const float* bo    = (const float*)d_in[16];
    float* out = (float*)d_out;

    void *pY = 0, *pWc = 0, *pbc = 0;
    cudaGetSymbolAddress(&pY, g_y);
    cudaGetSymbolAddress(&pWc, g_Wc);
    cudaGetSymbolAddress(&pbc, g_bc);
    cudaFuncSetAttribute(scan_kernel, cudaFuncAttributeMaxDynamicSharedMemorySize, SMEMSZ);

    prep_ew<<<128, 256>>>(emb, Wir, bir, Wiz, biz, Win, bin_);
    gemm128<<<8, 256>>>(Wh, Wo, (const float*)0, (float*)pWc);
    prep_misc<<<65, 256>>>(carry, bh, Wo, bo);
    scan_kernel<<<NCTA, TPB, SMEMSZ>>>(toks, Whr, Whz, Whn, bhn, carry, out);
    gemm128<<<256, 256>>>((const float*)pY, (const float*)pWc, (const float*)pbc,
                          out + 65536);
}

// round 15
// speedup vs baseline: 1.6737x; 1.6737x over previous
#include <cuda_runtime.h>
#include <cuda_bf16.h>
#include <math.h>

typedef unsigned long long ull;
typedef unsigned u32;

#define NCTA 128
#define TPB 512
#define WSROW 1032                      // bf16 per weight row (pad -> conflict-free)
#define WS_BYTES (2 * 24 * WSROW * 2)   // 99072
#define RED_BYTES (512 * 25 * 4)        // 51200
#define SMEMSZ (WS_BYTES + RED_BYTES)   // 150272

__device__ float g_EW[128 * 3 * 1024];
__device__ float g_Wc[1024 * 128];
__device__ float g_bc[128];
__device__ float g_y[64u * 512u * 1024u];
// h in mma A-fragment layout: [parity][plane][ktile 64][mtile 4][lane 32][reg 4] u32
__device__ __align__(16) u32 g_hF[2 * 2 * 64 * 4 * 128];
__device__ u32 g_cnt;

__device__ __forceinline__ u32 su32(const void* p) {
    u32 a;
    asm("{ .reg .u64 t; cvta.to.shared.u64 t, %1; cvt.u32.u64 %0, t; }" : "=r"(a) : "l"(p));
    return a;
}
__device__ __forceinline__ void ldgcg4(const u32* p, u32* r) {
    asm volatile("ld.global.cg.v4.u32 {%0,%1,%2,%3}, [%4];"
                 : "=r"(r[0]), "=r"(r[1]), "=r"(r[2]), "=r"(r[3]) : "l"(p));
}
__device__ __forceinline__ void ldsm2(u32 a, u32& r0, u32& r1) {
    asm volatile("ldmatrix.sync.aligned.m8n8.x2.shared.b16 {%0,%1}, [%2];"
                 : "=r"(r0), "=r"(r1) : "r"(a));
}
__device__ __forceinline__ void mma16816(float* d, const u32* a, const u32* b) {
    asm volatile("mma.sync.aligned.m16n8k16.row.col.f32.bf16.bf16.f32 "
        "{%0,%1,%2,%3},{%4,%5,%6,%7},{%8,%9},{%0,%1,%2,%3};"
        : "+f"(d[0]), "+f"(d[1]), "+f"(d[2]), "+f"(d[3])
        : "r"(a[0]), "r"(a[1]), "r"(a[2]), "r"(a[3]), "r"(b[0]), "r"(b[1]));
}
__device__ __forceinline__ float fsig(float x) {
    return __fdividef(1.0f, 1.0f + __expf(-x));
}
__device__ __forceinline__ float ftanh(float x) {
    float e = __expf(-2.0f * fabsf(x));
    float t = __fdividef(1.0f - e, 1.0f + e);
    return copysignf(t, x);
}
// fragment address (u32 index) for (parity, plane, b, kpair)
__device__ __forceinline__ u32 frag_idx(int par, int pl, int b, int kp) {
    int tk = kp >> 3, kpl = kp & 7;
    int tm = b >> 4, rl = b & 15;
    int lane = (rl & 7) * 4 + (kpl & 3);
    int reg = (rl >> 3) + 2 * (kpl >> 2);
    return (u32)(par * 65536 + pl * 32768 + tk * 512 + tm * 128 + lane * 4 + reg);
}

// ---------------- prep: EW table -------------------------------------------
__global__ __launch_bounds__(256) void prep_ew(
    const float* __restrict__ emb,
    const float* __restrict__ Wir, const float* __restrict__ bir,
    const float* __restrict__ Wiz, const float* __restrict__ biz,
    const float* __restrict__ Win, const float* __restrict__ bin_)
{
    __shared__ float se[128];
    int v = blockIdx.x, tid = threadIdx.x;
    if (tid < 128) se[tid] = emb[v * 128 + tid];
    __syncthreads();
    for (int i = tid; i < 3072; i += 256) {
        int g = i >> 10, j = i & 1023;
        const float* W  = (g == 0) ? Wir : (g == 1) ? Wiz : Win;
        const float* bb = (g == 0) ? bir : (g == 1) ? biz : bin_;
        float acc = bb[j];
        #pragma unroll 8
        for (int e = 0; e < 128; ++e) acc += se[e] * W[e * 1024 + j];
        g_EW[v * 3072 + i] = acc;
    }
}

// ---------------- prep: carry -> g_hF parity0, bc, counters -----------------
__global__ __launch_bounds__(256) void prep_misc(
    const float* __restrict__ carry, const float* __restrict__ bh,
    const float* __restrict__ Wo,    const float* __restrict__ bo)
{
    int bx = blockIdx.x, tid = threadIdx.x;
    if (bx < 64) {
        int b = bx;
        for (int kp = tid; kp < 512; kp += 256) {
            float f0 = carry[b * 1024 + 2 * kp];
            float f1 = carry[b * 1024 + 2 * kp + 1];
            __nv_bfloat16 h0 = __float2bfloat16(f0), h1 = __float2bfloat16(f1);
            __nv_bfloat16 l0 = __float2bfloat16(f0 - __bfloat162float(h0));
            __nv_bfloat16 l1 = __float2bfloat16(f1 - __bfloat162float(h1));
            g_hF[frag_idx(0, 0, b, kp)] =
                (u32)__bfloat16_as_ushort(h0) | ((u32)__bfloat16_as_ushort(h1) << 16);
            g_hF[frag_idx(0, 1, b, kp)] =
                (u32)__bfloat16_as_ushort(l0) | ((u32)__bfloat16_as_ushort(l1) << 16);
        }
    } else {
        if (tid < 128) {
            float acc = bo[tid];
            for (int m = 0; m < 1024; ++m) acc += bh[m] * Wo[m * 128 + tid];
            g_bc[tid] = acc;
        }
        if (tid == 0) g_cnt = 0u;
    }
}

// ---------------- tiled fp32 GEMM (Wc precompute + final logits) ------------
__global__ __launch_bounds__(256) void gemm128(
    const float* __restrict__ A, const float* __restrict__ Bm,
    const float* __restrict__ bias, float* __restrict__ C)
{
    __shared__ float As[32][132];
    __shared__ float Bs[32][128];
    int tid = threadIdx.x, tx = tid & 15, ty = tid >> 4, m0 = blockIdx.x * 128;
    float acc[8][8];
    #pragma unroll
    for (int i = 0; i < 8; ++i)
        #pragma unroll
        for (int j = 0; j < 8; ++j) acc[i][j] = bias ? bias[tx * 8 + j] : 0.0f;
    for (int k0 = 0; k0 < 1024; k0 += 32) {
        __syncthreads();
        #pragma unroll
        for (int i = 0; i < 4; ++i) {
            int idx = tid + i * 256, m = idx >> 3, q = idx & 7;
            float4 v = *(const float4*)(A + (size_t)(m0 + m) * 1024 + k0 + q * 4);
            As[q * 4 + 0][m] = v.x; As[q * 4 + 1][m] = v.y;
            As[q * 4 + 2][m] = v.z; As[q * 4 + 3][m] = v.w;
        }
        #pragma unroll
        for (int i = 0; i < 4; ++i) {
            int idx = tid + i * 256, r = idx >> 5, q = idx & 31;
            *(float4*)(&Bs[r][q * 4]) = *(const float4*)(Bm + (size_t)(k0 + r) * 128 + q * 4);
        }
        __syncthreads();
        #pragma unroll 4
        for (int kk = 0; kk < 32; ++kk) {
            float4 a0 = *(const float4*)(&As[kk][ty * 8]);
            float4 a1 = *(const float4*)(&As[kk][ty * 8 + 4]);
            float4 b0 = *(const float4*)(&Bs[kk][tx * 8]);
            float4 b1 = *(const float4*)(&Bs[kk][tx * 8 + 4]);
            float av[8] = {a0.x, a0.y, a0.z, a0.w, a1.x, a1.y, a1.z, a1.w};
            float bv[8] = {b0.x, b0.y, b0.z, b0.w, b1.x, b1.y, b1.z, b1.w};
            #pragma unroll
            for (int i = 0; i < 8; ++i)
                #pragma unroll
                for (int j = 0; j < 8; ++j) acc[i][j] = fmaf(av[i], bv[j], acc[i][j]);
        }
    }
    #pragma unroll
    for (int i = 0; i < 8; ++i) {
        float* cp = C + (size_t)(m0 + ty * 8 + i) * 128 + tx * 8;
        *(float4*)cp       = make_float4(acc[i][0], acc[i][1], acc[i][2], acc[i][3]);
        *(float4*)(cp + 4) = make_float4(acc[i][4], acc[i][5], acc[i][6], acc[i][7]);
    }
}

// ---------------- persistent mma.sync GRU scan (fragment-layout h) ----------
__global__ void __launch_bounds__(TPB, 1) scan_kernel(
    const int* __restrict__ toks,
    const float* __restrict__ Whr, const float* __restrict__ Whz,
    const float* __restrict__ Whn, const float* __restrict__ bhn,
    const float* __restrict__ carry, float* __restrict__ outc)
{
    extern __shared__ char sm[];
    __nv_bfloat16* Ws = (__nv_bfloat16*)sm;
    const u32 smb = su32(sm);
    float* red = (float*)(sm + WS_BYTES);

    const int tid = threadIdx.x, bx = blockIdx.x;
    const int lane = tid & 31, w = tid >> 5;
    const int kq = w >> 1, mpair = w & 1;    // kq 0..7: ktiles kq, kq+8, ..., kq+56
    const int j0 = bx * 8;
    const int c0 = (lane & 3) * 2;

    // ---- weights -> smem bf16 hi/lo, once ----
    for (int idx = tid; idx < 24 * 1024; idx += TPB) {
        int c = idx >> 10, k = idx & 1023;
        int g = c >> 3, jl = c & 7;
        const float* Wg = (g == 0) ? Whr : (g == 1) ? Whz : Whn;
        float wv = Wg[(size_t)k * 1024 + j0 + jl];
        __nv_bfloat16 hi = __float2bfloat16(wv);
        Ws[c * WSROW + k] = hi;
        Ws[24 * WSROW + c * WSROW + k] = __float2bfloat16(wv - __bfloat162float(hi));
    }

    // ---- update owners: warps kq<4 ----
    const bool owner = (kq < 4);
    const int mt_o = kq & 1, h2_o = (kq >> 1) & 1;
    const int b_o = 32 * mpair + 16 * mt_o + (lane >> 2) + 8 * h2_o;
    const int kp_o = (j0 + c0) >> 1;
    float hreg[2], bhn2[2];
    u32 fi_hi = 0, fi_lo = 0;
    if (owner) {
        bhn2[0] = bhn[j0 + c0]; bhn2[1] = bhn[j0 + c0 + 1];
        hreg[0] = carry[b_o * 1024 + j0 + c0];
        hreg[1] = carry[b_o * 1024 + j0 + c0 + 1];
        fi_hi = frag_idx(0, 0, b_o, kp_o);   // parity offset added per step
        fi_lo = frag_idx(0, 1, b_o, kp_o);
    }
    __syncthreads();

    // per-thread A-fragment base offset (u32 units), within [plane][tk][tm] grid
    const u32 aoff = (u32)((mpair * 2) * 128 + lane * 4);
    const u32 bAddr0 = smb + ((lane & 7) * WSROW) * 2 + ((lane >> 3) & 1) * 16;

    for (int t = 0; t < 512; ++t) {
        const int p = t & 1;
        const u32* hfp = g_hF + p * 65536;

        // prefetch token + EW rows for the tail
        float2 er, ez, en;
        if (owner) {
            int tok = toks[b_o * 512 + t];
            const float* ewp = g_EW + (size_t)tok * 3072 + j0 + c0;
            er = *(const float2*)ewp;
            ez = *(const float2*)(ewp + 1024);
            en = *(const float2*)(ewp + 2048);
        }

        float acc[2][3][4];
        float* accf = &acc[0][0][0];
        #pragma unroll
        for (int i = 0; i < 24; ++i) accf[i] = 0.0f;

        // register double-buffered A fragments
        u32 Acur[2][2][4], Anxt[2][2][4];   // [plane][mt][4]
        {
            const int tk = kq;
            #pragma unroll
            for (int pl = 0; pl < 2; ++pl)
                #pragma unroll
                for (int mt = 0; mt < 2; ++mt)
                    ldgcg4(hfp + pl * 32768 + tk * 512 + aoff + mt * 128, Acur[pl][mt]);
        }

        #pragma unroll
        for (int s = 0; s < 8; ++s) {
            const int tk = kq + s * 8;
            if (s < 7) {
                const int tkn = tk + 8;
                #pragma unroll
                for (int pl = 0; pl < 2; ++pl)
                    #pragma unroll
                    for (int mt = 0; mt < 2; ++mt)
                        ldgcg4(hfp + pl * 32768 + tkn * 512 + aoff + mt * 128, Anxt[pl][mt]);
            }
            u32 bH[3][2], bL[3][2];
            #pragma unroll
            for (int nt = 0; nt < 3; ++nt) {
                u32 b = bAddr0 + nt * (8 * WSROW * 2) + tk * 32;
                ldsm2(b, bH[nt][0], bH[nt][1]);
                ldsm2(b + 24 * WSROW * 2, bL[nt][0], bL[nt][1]);
            }
            #pragma unroll
            for (int mt = 0; mt < 2; ++mt)
                #pragma unroll
                for (int nt = 0; nt < 3; ++nt) {
                    mma16816(acc[mt][nt], Acur[0][mt], bH[nt]);
                    mma16816(acc[mt][nt], Acur[0][mt], bL[nt]);
                    mma16816(acc[mt][nt], Acur[1][mt], bH[nt]);
                }
            if (s < 7) {
                #pragma unroll
                for (int pl = 0; pl < 2; ++pl)
                    #pragma unroll
                    for (int mt = 0; mt < 2; ++mt)
                        #pragma unroll
                        for (int r = 0; r < 4; ++r)
                            Acur[pl][mt][r] = Anxt[pl][mt][r];
            }
        }

        // ---- publish partials (rows padded to 25 floats: conflict-free) ----
        {
            float* rp = red + tid * 25;
            #pragma unroll
            for (int i = 0; i < 24; ++i) rp[i] = accf[i];
        }
        __syncthreads();

        // ---- owners: gather 8 partials (scalar loads: 25-stride is odd), update
        if (owner) {
            float s6[6];
            #pragma unroll
            for (int nt = 0; nt < 3; ++nt) {
                float v0 = 0.0f, v1 = 0.0f;
                int idx = mt_o * 12 + nt * 4 + 2 * h2_o;
                #pragma unroll
                for (int q2 = 0; q2 < 8; ++q2) {
                    const float* rp = red + ((q2 * 2 + mpair) * 32 + lane) * 25 + idx;
                    v0 += rp[0];
                    v1 += rp[1];
                }
                s6[nt * 2] = v0; s6[nt * 2 + 1] = v1;
            }
            float hn[2];
            #pragma unroll
            for (int i = 0; i < 2; ++i) {
                float rr = fsig((i ? er.y : er.x) + s6[0 + i]);
                float zz = fsig((i ? ez.y : ez.x) + s6[2 + i]);
                float nn = ftanh((i ? en.y : en.x) + rr * (s6[4 + i] + bhn2[i]));
                hn[i] = (1.0f - zz) * nn + zz * hreg[i];
                hreg[i] = hn[i];
            }
            *(float2*)(g_y + (size_t)(b_o * 512 + t) * 1024 + j0 + c0) =
                make_float2(hn[0], hn[1]);
            __nv_bfloat16 h0 = __float2bfloat16(hn[0]);
            __nv_bfloat16 h1 = __float2bfloat16(hn[1]);
            __nv_bfloat16 l0 = __float2bfloat16(hn[0] - __bfloat162float(h0));
            __nv_bfloat16 l1 = __float2bfloat16(hn[1] - __bfloat162float(h1));
            u32 po = (u32)((p ^ 1) * 65536);
            g_hF[po + fi_hi] =
                (u32)__bfloat16_as_ushort(h0) | ((u32)__bfloat16_as_ushort(h1) << 16);
            g_hF[po + fi_lo] =
                (u32)__bfloat16_as_ushort(l0) | ((u32)__bfloat16_as_ushort(l1) << 16);
            if (t == 511)
                *(float2*)(outc + b_o * 1024 + j0 + c0) = make_float2(hn[0], hn[1]);
        }

        // ---- grid barrier (arrive with release; poll counter directly) ----
        __syncthreads();
        if (tid == 0) {
            u32 target = (u32)(t + 1) * (u32)NCTA, old;
            asm volatile("atom.acq_rel.gpu.add.u32 %0, [%1], 1;"
                         : "=r"(old) : "l"(&g_cnt) : "memory");
            if (old != target - 1u) {
                u32 v;
                do {
                    asm volatile("ld.acquire.gpu.u32 %0, [%1];" : "=r"(v) : "l"(&g_cnt) : "memory");
                } while (v < target);
            }
        }
        __syncthreads();
    }
}

// ---------------- launch ----------------------------------------------------
extern "C" void kernel_launch(void* const* d_in, const int* in_sizes, int n_in,
                              void* d_out, int out_size)
{
    const int*   toks  = (const int*)  d_in[0];
    const float* carry = (const float*)d_in[1];
    const float* emb   = (const float*)d_in[2];
    const float* Wir   = (const float*)d_in[3];
    const float* bir   = (const float*)d_in[4];
    const float* Whr   = (const float*)d_in[5];
    const float* Wiz   = (const float*)d_in[6];
    const float* biz   = (const float*)d_in[7];
    const float* Whz   = (const float*)d_in[8];
    const float* Win   = (const float*)d_in[9];
    const float* bin_  = (const float*)d_in[10];
    const float* Whn   = (const float*)d_in[11];
    const float* bhn   = (const float*)d_in[12];
    const float* Wh    = (const float*)d_in[13];
    const float* bh    = (const float*)d_in[14];
    const float* Wo    = (const float*)d_in[15];
    const float* bo    = (const float*)d_in[16];
    float* out = (float*)d_out;

    void *pY = 0, *pWc = 0, *pbc = 0;
    cudaGetSymbolAddress(&pY, g_y);
    cudaGetSymbolAddress(&pWc, g_Wc);
    cudaGetSymbolAddress(&pbc, g_bc);
    cudaFuncSetAttribute(scan_kernel, cudaFuncAttributeMaxDynamicSharedMemorySize, SMEMSZ);

    prep_ew<<<128, 256>>>(emb, Wir, bir, Wiz, biz, Win, bin_);
    gemm128<<<8, 256>>>(Wh, Wo, (const float*)0, (float*)pWc);
    prep_misc<<<65, 256>>>(carry, bh, Wo, bo);
    scan_kernel<<<NCTA, TPB, SMEMSZ>>>(toks, Whr, Whz, Whn, bhn, carry, out);
    gemm128<<<256, 256>>>((const float*)pY, (const float*)pWc, (const float*)pbc,
                          out + 65536);
}

// round 17
// speedup vs baseline: 1.7673x; 1.0559x over previous
#include <cuda_runtime.h>
#include <cuda_bf16.h>
#include <math.h>

typedef unsigned long long ull;
typedef unsigned u32;

#define NCTA 128
#define TPB 512
#define WSROW 1032                      // bf16 per weight row (pad -> conflict-free)
#define WS_BYTES (2 * 24 * WSROW * 2)   // 99072
#define RED_BYTES (512 * 25 * 4)        // 51200
#define SMEMSZ (WS_BYTES + RED_BYTES)   // 150272

// gemm_out smem: 3 bufs x (A plane-pair) + 3 bufs x (B plane-pair)
#define GROWB 144                       // 72 bf16 per staged row (64 data + pad)
#define GPLANE (128 * GROWB)            // 18432
#define GBUF (2 * GPLANE)               // 36864
#define GB_OFF (3 * GBUF)               // 110592 (B region base)
#define GSMEM (6 * GBUF)                // 221184

__device__ float g_EW[128 * 3 * 1024];
__device__ float g_bc[128];
__device__ __nv_bfloat16 g_WcT[2 * 128 * 1024];      // [plane][n][k]
__device__ __align__(16) u32 g_yA[2u * 16777216u];   // y bf16 planes [plane][m][k]/2
// h in mma A-fragment layout: [parity][plane][ktile 64][mtile 4][lane 32][reg 4] u32
__device__ __align__(16) u32 g_hF[2 * 2 * 64 * 4 * 128];
__device__ u32 g_cnt;

__device__ __forceinline__ u32 su32(const void* p) {
    u32 a;
    asm("{ .reg .u64 t; cvta.to.shared.u64 t, %1; cvt.u32.u64 %0, t; }" : "=r"(a) : "l"(p));
    return a;
}
__device__ __forceinline__ void cpa16(u32 d, const void* s) {
    asm volatile("cp.async.cg.shared.global [%0], [%1], 16;" :: "r"(d), "l"(s));
}
__device__ __forceinline__ void ldgcg4(const u32* p, u32* r) {
    asm volatile("ld.global.cg.v4.u32 {%0,%1,%2,%3}, [%4];"
                 : "=r"(r[0]), "=r"(r[1]), "=r"(r[2]), "=r"(r[3]) : "l"(p));
}
__device__ __forceinline__ void ldsm4(u32 a, u32& r0, u32& r1, u32& r2, u32& r3) {
    asm volatile("ldmatrix.sync.aligned.m8n8.x4.shared.b16 {%0,%1,%2,%3}, [%4];"
                 : "=r"(r0), "=r"(r1), "=r"(r2), "=r"(r3) : "r"(a));
}
__device__ __forceinline__ void ldsm2(u32 a, u32& r0, u32& r1) {
    asm volatile("ldmatrix.sync.aligned.m8n8.x2.shared.b16 {%0,%1}, [%2];"
                 : "=r"(r0), "=r"(r1) : "r"(a));
}
__device__ __forceinline__ void mma16816(float* d, const u32* a, const u32* b) {
    asm volatile("mma.sync.aligned.m16n8k16.row.col.f32.bf16.bf16.f32 "
        "{%0,%1,%2,%3},{%4,%5,%6,%7},{%8,%9},{%0,%1,%2,%3};"
        : "+f"(d[0]), "+f"(d[1]), "+f"(d[2]), "+f"(d[3])
        : "r"(a[0]), "r"(a[1]), "r"(a[2]), "r"(a[3]), "r"(b[0]), "r"(b[1]));
}
__device__ __forceinline__ float fsig(float x) {
    return __fdividef(1.0f, 1.0f + __expf(-x));
}
__device__ __forceinline__ float ftanh(float x) {
    float e = __expf(-2.0f * fabsf(x));
    float t = __fdividef(1.0f - e, 1.0f + e);
    return copysignf(t, x);
}
__device__ __forceinline__ u32 frag_idx(int par, int pl, int b, int kp) {
    int tk = kp >> 3, kpl = kp & 7;
    int tm = b >> 4, rl = b & 15;
    int lane = (rl & 7) * 4 + (kpl & 3);
    int reg = (rl >> 3) + 2 * (kpl >> 2);
    return (u32)(par * 65536 + pl * 32768 + tk * 512 + tm * 128 + lane * 4 + reg);
}

// ---------------- prep: EW table -------------------------------------------
__global__ __launch_bounds__(256) void prep_ew(
    const float* __restrict__ emb,
    const float* __restrict__ Wir, const float* __restrict__ bir,
    const float* __restrict__ Wiz, const float* __restrict__ biz,
    const float* __restrict__ Win, const float* __restrict__ bin_)
{
    __shared__ float se[128];
    int v = blockIdx.x, tid = threadIdx.x;
    if (tid < 128) se[tid] = emb[v * 128 + tid];
    __syncthreads();
    for (int i = tid; i < 3072; i += 256) {
        int g = i >> 10, j = i & 1023;
        const float* W  = (g == 0) ? Wir : (g == 1) ? Wiz : Win;
        const float* bb = (g == 0) ? bir : (g == 1) ? biz : bin_;
        float acc = bb[j];
        #pragma unroll 8
        for (int e = 0; e < 128; ++e) acc += se[e] * W[e * 1024 + j];
        g_EW[v * 3072 + i] = acc;
    }
}

// ---------------- prep: Wc = Wh @ Wo -> bf16 hi/lo transposed planes --------
__global__ __launch_bounds__(128) void gemm_wc(
    const float* __restrict__ Wh, const float* __restrict__ Wo)
{
    __shared__ float wh[16][1024];
    int bx = blockIdx.x, tid = threadIdx.x;   // 64 CTAs, 16 k-rows each
    int r0 = bx * 16;
    for (int i = tid; i < 4096; i += 128)
        ((float4*)&wh[0][0])[i] = ((const float4*)(Wh + (size_t)r0 * 1024))[i];
    __syncthreads();
    int n = tid;
    float acc[16];
    #pragma unroll
    for (int r = 0; r < 16; ++r) acc[r] = 0.0f;
    for (int m = 0; m < 1024; ++m) {
        float wo = Wo[(size_t)m * 128 + n];
        #pragma unroll
        for (int r = 0; r < 16; ++r) acc[r] = fmaf(wh[r][m], wo, acc[r]);
    }
    #pragma unroll
    for (int r = 0; r < 16; ++r) {
        __nv_bfloat16 hi = __float2bfloat16(acc[r]);
        __nv_bfloat16 lo = __float2bfloat16(acc[r] - __bfloat162float(hi));
        g_WcT[n * 1024 + r0 + r] = hi;
        g_WcT[131072 + n * 1024 + r0 + r] = lo;
    }
}

// ---------------- prep: carry -> g_hF parity0, bc, counters -----------------
__global__ __launch_bounds__(256) void prep_misc(
    const float* __restrict__ carry, const float* __restrict__ bh,
    const float* __restrict__ Wo,    const float* __restrict__ bo)
{
    int bx = blockIdx.x, tid = threadIdx.x;
    if (bx < 64) {
        int b = bx;
        for (int kp = tid; kp < 512; kp += 256) {
            float f0 = carry[b * 1024 + 2 * kp];
            float f1 = carry[b * 1024 + 2 * kp + 1];
            __nv_bfloat16 h0 = __float2bfloat16(f0), h1 = __float2bfloat16(f1);
            __nv_bfloat16 l0 = __float2bfloat16(f0 - __bfloat162float(h0));
            __nv_bfloat16 l1 = __float2bfloat16(f1 - __bfloat162float(h1));
            g_hF[frag_idx(0, 0, b, kp)] =
                (u32)__bfloat16_as_ushort(h0) | ((u32)__bfloat16_as_ushort(h1) << 16);
            g_hF[frag_idx(0, 1, b, kp)] =
                (u32)__bfloat16_as_ushort(l0) | ((u32)__bfloat16_as_ushort(l1) << 16);
        }
    } else {
        if (tid < 128) {
            float acc = bo[tid];
            for (int m = 0; m < 1024; ++m) acc += bh[m] * Wo[m * 128 + tid];
            g_bc[tid] = acc;
        }
        if (tid == 0) g_cnt = 0u;
    }
}

// ---------------- persistent mma.sync GRU scan (fragment-layout h) ----------
__global__ void __launch_bounds__(TPB, 1) scan_kernel(
    const int* __restrict__ toks,
    const float* __restrict__ Whr, const float* __restrict__ Whz,
    const float* __restrict__ Whn, const float* __restrict__ bhn,
    const float* __restrict__ carry, float* __restrict__ outc)
{
    extern __shared__ char sm[];
    __nv_bfloat16* Ws = (__nv_bfloat16*)sm;
    const u32 smb = su32(sm);
    float* red = (float*)(sm + WS_BYTES);

    const int tid = threadIdx.x, bx = blockIdx.x;
    const int lane = tid & 31, w = tid >> 5;
    const int kq = w >> 1, mpair = w & 1;
    const int j0 = bx * 8;
    const int c0 = (lane & 3) * 2;

    for (int idx = tid; idx < 24 * 1024; idx += TPB) {
        int c = idx >> 10, k = idx & 1023;
        int g = c >> 3, jl = c & 7;
        const float* Wg = (g == 0) ? Whr : (g == 1) ? Whz : Whn;
        float wv = Wg[(size_t)k * 1024 + j0 + jl];
        __nv_bfloat16 hi = __float2bfloat16(wv);
        Ws[c * WSROW + k] = hi;
        Ws[24 * WSROW + c * WSROW + k] = __float2bfloat16(wv - __bfloat162float(hi));
    }

    const bool owner = (kq < 4);
    const int mt_o = kq & 1, h2_o = (kq >> 1) & 1;
    const int b_o = 32 * mpair + 16 * mt_o + (lane >> 2) + 8 * h2_o;
    const int kp_o = (j0 + c0) >> 1;
    float hreg[2], bhn2[2];
    u32 fi_hi = 0, fi_lo = 0, yi = 0;
    if (owner) {
        bhn2[0] = bhn[j0 + c0]; bhn2[1] = bhn[j0 + c0 + 1];
        hreg[0] = carry[b_o * 1024 + j0 + c0];
        hreg[1] = carry[b_o * 1024 + j0 + c0 + 1];
        fi_hi = frag_idx(0, 0, b_o, kp_o);
        fi_lo = frag_idx(0, 1, b_o, kp_o);
    }
    __syncthreads();

    const u32 aoff = (u32)((mpair * 2) * 128 + lane * 4);
    const u32 bAddr0 = smb + ((lane & 7) * WSROW) * 2 + ((lane >> 3) & 1) * 16;

    for (int t = 0; t < 512; ++t) {
        const int p = t & 1;
        const u32* hfp = g_hF + p * 65536;

        float2 er, ez, en;
        if (owner) {
            int tok = toks[b_o * 512 + t];
            const float* ewp = g_EW + (size_t)tok * 3072 + j0 + c0;
            er = *(const float2*)ewp;
            ez = *(const float2*)(ewp + 1024);
            en = *(const float2*)(ewp + 2048);
            yi = ((u32)(b_o * 512 + t) * 1024u + (u32)(j0 + c0)) >> 1;
        }

        float acc[2][3][4];
        float* accf = &acc[0][0][0];
        #pragma unroll
        for (int i = 0; i < 24; ++i) accf[i] = 0.0f;

        u32 Acur[2][2][4], Anxt[2][2][4];
        {
            const int tk = kq;
            #pragma unroll
            for (int pl = 0; pl < 2; ++pl)
                #pragma unroll
                for (int mt = 0; mt < 2; ++mt)
                    ldgcg4(hfp + pl * 32768 + tk * 512 + aoff + mt * 128, Acur[pl][mt]);
        }

        #pragma unroll
        for (int s = 0; s < 8; ++s) {
            const int tk = kq + s * 8;
            if (s < 7) {
                const int tkn = tk + 8;
                #pragma unroll
                for (int pl = 0; pl < 2; ++pl)
                    #pragma unroll
                    for (int mt = 0; mt < 2; ++mt)
                        ldgcg4(hfp + pl * 32768 + tkn * 512 + aoff + mt * 128, Anxt[pl][mt]);
            }
            u32 bH[3][2], bL[3][2];
            #pragma unroll
            for (int nt = 0; nt < 3; ++nt) {
                u32 b = bAddr0 + nt * (8 * WSROW * 2) + tk * 32;
                ldsm2(b, bH[nt][0], bH[nt][1]);
                ldsm2(b + 24 * WSROW * 2, bL[nt][0], bL[nt][1]);
            }
            #pragma unroll
            for (int mt = 0; mt < 2; ++mt)
                #pragma unroll
                for (int nt = 0; nt < 3; ++nt) {
                    mma16816(acc[mt][nt], Acur[0][mt], bH[nt]);
                    mma16816(acc[mt][nt], Acur[0][mt], bL[nt]);
                    mma16816(acc[mt][nt], Acur[1][mt], bH[nt]);
                }
            if (s < 7) {
                #pragma unroll
                for (int pl = 0; pl < 2; ++pl)
                    #pragma unroll
                    for (int mt = 0; mt < 2; ++mt)
                        #pragma unroll
                        for (int r = 0; r < 4; ++r)
                            Acur[pl][mt][r] = Anxt[pl][mt][r];
            }
        }

        {
            float* rp = red + tid * 25;
            #pragma unroll
            for (int i = 0; i < 24; ++i) rp[i] = accf[i];
        }
        __syncthreads();

        if (owner) {
            float s6[6];
            #pragma unroll
            for (int nt = 0; nt < 3; ++nt) {
                float v0 = 0.0f, v1 = 0.0f;
                int idx = mt_o * 12 + nt * 4 + 2 * h2_o;
                #pragma unroll
                for (int q2 = 0; q2 < 8; ++q2) {
                    const float* rp = red + ((q2 * 2 + mpair) * 32 + lane) * 25 + idx;
                    v0 += rp[0];
                    v1 += rp[1];
                }
                s6[nt * 2] = v0; s6[nt * 2 + 1] = v1;
            }
            float hn[2];
            #pragma unroll
            for (int i = 0; i < 2; ++i) {
                float rr = fsig((i ? er.y : er.x) + s6[0 + i]);
                float zz = fsig((i ? ez.y : ez.x) + s6[2 + i]);
                float nn = ftanh((i ? en.y : en.x) + rr * (s6[4 + i] + bhn2[i]));
                hn[i] = (1.0f - zz) * nn + zz * hreg[i];
                hreg[i] = hn[i];
            }
            __nv_bfloat16 h0 = __float2bfloat16(hn[0]);
            __nv_bfloat16 h1 = __float2bfloat16(hn[1]);
            __nv_bfloat16 l0 = __float2bfloat16(hn[0] - __bfloat162float(h0));
            __nv_bfloat16 l1 = __float2bfloat16(hn[1] - __bfloat162float(h1));
            u32 hp = (u32)__bfloat16_as_ushort(h0) | ((u32)__bfloat16_as_ushort(h1) << 16);
            u32 lp = (u32)__bfloat16_as_ushort(l0) | ((u32)__bfloat16_as_ushort(l1) << 16);
            g_yA[yi] = hp;
            g_yA[16777216u + yi] = lp;
            u32 po = (u32)((p ^ 1) * 65536);
            g_hF[po + fi_hi] = hp;
            g_hF[po + fi_lo] = lp;
            if (t == 511)
                *(float2*)(outc + b_o * 1024 + j0 + c0) = make_float2(hn[0], hn[1]);
        }

        __syncthreads();
        if (tid == 0) {
            u32 target = (u32)(t + 1) * (u32)NCTA, old;
            asm volatile("atom.acq_rel.gpu.add.u32 %0, [%1], 1;"
                         : "=r"(old) : "l"(&g_cnt) : "memory");
            if (old != target - 1u) {
                u32 v;
                do {
                    asm volatile("ld.acquire.gpu.u32 %0, [%1];" : "=r"(v) : "l"(&g_cnt) : "memory");
                } while (v < target);
            }
        }
        __syncthreads();
    }
}

// ---------------- gemm_out staging helper -----------------------------------
__device__ __forceinline__ void gstage(u32 smb, int m0, int buf, int kc, int tid)
{
    #pragma unroll
    for (int i2 = 0; i2 < 8; ++i2) {
        int u = tid + i2 * 256;
        int pl = u >> 10, rem = u & 1023, r = rem >> 3, s = rem & 7;
        cpa16(smb + buf * GBUF + pl * GPLANE + r * GROWB + s * 16,
              g_yA + pl * 16777216u + (size_t)(m0 + r) * 512 + kc * 32 + s * 4);
        cpa16(smb + GB_OFF + buf * GBUF + pl * GPLANE + r * GROWB + s * 16,
              g_WcT + pl * 131072 + (size_t)r * 1024 + kc * 64 + s * 8);
    }
    asm volatile("cp.async.commit_group;" ::: "memory");
}

// ---------------- logits GEMM: C = y @ Wc + bc  (bf16 3-term mma) -----------
__global__ void __launch_bounds__(256, 1) gemm_out(float* __restrict__ C)
{
    extern __shared__ char sg[];
    const u32 smb = su32(sg);
    const int tid = threadIdx.x, bx = blockIdx.x;
    const int lane = tid & 31, w = tid >> 5;
    const int m0 = bx * 128;

    float acc[16][4];
    #pragma unroll
    for (int nt = 0; nt < 16; ++nt)
        #pragma unroll
        for (int i = 0; i < 4; ++i) acc[nt][i] = 0.0f;

    gstage(smb, m0, 0, 0, tid);
    gstage(smb, m0, 1, 1, tid);

    const u32 aA0 = smb + (u32)((w * 16 + (lane & 15)) * GROWB + (lane >> 4) * 16);
    const u32 bA0 = smb + GB_OFF + (u32)(((lane & 7)) * GROWB + ((lane >> 3) & 1) * 16);

    #pragma unroll 1
    for (int c = 0; c < 16; ++c) {
        if (c < 15) asm volatile("cp.async.wait_group 1;" ::: "memory");
        else        asm volatile("cp.async.wait_group 0;" ::: "memory");
        __syncthreads();
        if (c < 14) gstage(smb, m0, (c + 2) % 3, c + 2, tid);
        const u32 abuf = aA0 + (u32)((c % 3) * GBUF);
        const u32 bbuf = bA0 + (u32)((c % 3) * GBUF);
        #pragma unroll
        for (int ks = 0; ks < 4; ++ks) {
            u32 aH[4], aL[4];
            ldsm4(abuf + ks * 32, aH[0], aH[1], aH[2], aH[3]);
            ldsm4(abuf + GPLANE + ks * 32, aL[0], aL[1], aL[2], aL[3]);
            #pragma unroll
            for (int nt = 0; nt < 16; ++nt) {
                u32 bH[2], bL[2];
                u32 ba = bbuf + nt * (8 * GROWB) + ks * 32;
                ldsm2(ba, bH[0], bH[1]);
                ldsm2(ba + GPLANE, bL[0], bL[1]);
                mma16816(acc[nt], aH, bH);
                mma16816(acc[nt], aH, bL);
                mma16816(acc[nt], aL, bH);
            }
        }
        __syncthreads();
    }

    const int row0 = m0 + w * 16 + (lane >> 2);
    #pragma unroll
    for (int nt = 0; nt < 16; ++nt) {
        int n = nt * 8 + (lane & 3) * 2;
        float b0 = g_bc[n], b1 = g_bc[n + 1];
        *(float2*)(C + (size_t)row0 * 128 + n) =
            make_float2(acc[nt][0] + b0, acc[nt][1] + b1);
        *(float2*)(C + (size_t)(row0 + 8) * 128 + n) =
            make_float2(acc[nt][2] + b0, acc[nt][3] + b1);
    }
}

// ---------------- launch ----------------------------------------------------
extern "C" void kernel_launch(void* const* d_in, const int* in_sizes, int n_in,
                              void* d_out, int out_size)
{
    const int*   toks  = (const int*)  d_in[0];
    const float* carry = (const float*)d_in[1];
    const float* emb   = (const float*)d_in[2];
    const float* Wir   = (const float*)d_in[3];
    const float* bir   = (const float*)d_in[4];
    const float* Whr   = (const float*)d_in[5];
    const float* Wiz   = (const float*)d_in[6];
    const float* biz   = (const float*)d_in[7];
    const float* Whz   = (const float*)d_in[8];
    const float* Win   = (const float*)d_in[9];
    const float* bin_  = (const float*)d_in[10];
    const float* Whn   = (const float*)d_in[11];
    const float* bhn   = (const float*)d_in[12];
    const float* Wh    = (const float*)d_in[13];
    const float* bh    = (const float*)d_in[14];
    const float* Wo    = (const float*)d_in[15];
    const float* bo    = (const float*)d_in[16];
    float* out = (float*)d_out;

    cudaFuncSetAttribute(scan_kernel, cudaFuncAttributeMaxDynamicSharedMemorySize, SMEMSZ);
    cudaFuncSetAttribute(gemm_out, cudaFuncAttributeMaxDynamicSharedMemorySize, GSMEM);

    prep_ew<<<128, 256>>>(emb, Wir, bir, Wiz, biz, Win, bin_);
    gemm_wc<<<64, 128>>>(Wh, Wo);
    prep_misc<<<65, 256>>>(carry, bh, Wo, bo);
    scan_kernel<<<NCTA, TPB, SMEMSZ>>>(toks, Whr, Whz, Whn, bhn, carry, out);
    gemm_out<<<256, 256, GSMEM>>>(out + 65536);
}